// round 1
// baseline (speedup 1.0000x reference)
#include <cuda_runtime.h>
#include <cuda_bf16.h>
#include <cstddef>

#define NN 200000
#define EMBD 128

// ---------------- scratch (device globals; no allocation) ----------------
__device__ float g_h [(size_t)NN * EMBD];   // current node rep
__device__ float g_P [(size_t)NN * EMBD];   // relu(xl) messages
__device__ float g_A [(size_t)NN * EMBD];   // agg buffer 1
__device__ float g_B [(size_t)NN * EMBD];   // agg buffer 2
__device__ float g_H1[(size_t)NN * 256];    // encoder hidden
__device__ float g_deg0[NN], g_deg1[NN];
__device__ float g_dis0[NN], g_dis1[NN];    // deg^-0.5
__device__ float g_dinv0[NN], g_dinv1[NN];  // 1/deg

__device__ __forceinline__ float leaky_f(float v) { return v >= 0.f ? v : 0.1f * v; }
__device__ __forceinline__ float relu_f(float v)  { return v > 0.f ? v : 0.f; }

// ---------------- degree kernels ----------------
__global__ void k_initdeg() {
    int i = blockIdx.x * 256 + threadIdx.x;
    if (i < NN) { g_deg0[i] = 1.f; g_deg1[i] = 1.f; }
}

__global__ void k_count(const int* __restrict__ edges, float* __restrict__ deg, int E) {
    int i = blockIdx.x * 256 + threadIdx.x;
    if (i < E) atomicAdd(&deg[edges[i]], 1.f);   // rows are edges[0..E)
}

__global__ void k_finishdeg() {
    int i = blockIdx.x * 256 + threadIdx.x;
    if (i < NN) {
        float d0 = g_deg0[i], d1 = g_deg1[i];
        g_dis0[i] = rsqrtf(d0); g_dinv0[i] = 1.0f / d0;
        g_dis1[i] = rsqrtf(d1); g_dinv1[i] = 1.0f / d1;
    }
}

// ---------------- encoder layer 1: H1 = leaky(x @ W1 + b1), K=32, Nout=256 ----------------
__global__ void k_enc1(const float* __restrict__ x, const float* __restrict__ W1,
                       const float* __restrict__ b1) {
    __shared__ float sW[32 * 256];
    int t = threadIdx.x;
    {
        float4* sv = (float4*)sW;
        const float4* wv = (const float4*)W1;
        #pragma unroll
        for (int i = 0; i < 8; i++) sv[t + 256 * i] = wv[t + 256 * i];
    }
    __syncthreads();
    int wid = t >> 5, lane = t & 31;
    int node = blockIdx.x * 8 + wid;
    float xv = x[(size_t)node * 32 + lane];
    float acc[8];
    #pragma unroll
    for (int i = 0; i < 8; i++) acc[i] = b1[lane + 32 * i];
    #pragma unroll
    for (int k = 0; k < 32; k++) {
        float xk = __shfl_sync(0xffffffffu, xv, k);
        #pragma unroll
        for (int i = 0; i < 8; i++) acc[i] += xk * sW[k * 256 + lane + 32 * i];
    }
    float* dst = g_H1 + (size_t)node * 256;
    #pragma unroll
    for (int i = 0; i < 8; i++) dst[lane + 32 * i] = leaky_f(acc[i]);
}

// ---------------- generic GEMM: C[64 x 128] tile of A[M,K] @ W[K,128] ----------------
// mode 0: h = leaky(acc + bias) -> AGG; also out[r*512 + c] for r < NI  (encoder layer 2)
// mode 1: P = relu(acc+bias); AGG = relu(acc+bias+root) * dinv[r]       (GCN linear)
__global__ void k_gemm(const float* __restrict__ A, const float* __restrict__ W,
                       const float* __restrict__ bias, const float* __restrict__ root,
                       const float* __restrict__ dinv, float* __restrict__ P,
                       float* __restrict__ AGG, float* __restrict__ out,
                       int K, int mode, int NI) {
    __shared__ float sA[64 * 64];
    __shared__ float sW[64 * 128];
    int t = threadIdx.x;
    int tx = t & 31, ty = t >> 5;
    int r0 = blockIdx.x * 64;
    float acc[8][4];
    #pragma unroll
    for (int i = 0; i < 8; i++)
        #pragma unroll
        for (int j = 0; j < 4; j++) acc[i][j] = 0.f;

    for (int kc = 0; kc < K; kc += 64) {
        // load A tile: 64 rows x 64 cols (4 float4 per thread)
        #pragma unroll
        for (int i = 0; i < 4; i++) {
            int idx = t + 256 * i;
            int r = idx >> 4, c = idx & 15;
            ((float4*)sA)[idx] = *(const float4*)(A + (size_t)(r0 + r) * K + kc + c * 4);
        }
        // load W tile: 64 rows x 128 cols (8 float4 per thread)
        #pragma unroll
        for (int i = 0; i < 8; i++) {
            int idx = t + 256 * i;
            int r = idx >> 5, c = idx & 31;
            ((float4*)sW)[idx] = *(const float4*)(W + (size_t)(kc + r) * 128 + c * 4);
        }
        __syncthreads();
        #pragma unroll
        for (int k = 0; k < 64; k++) {
            float4 w = ((float4*)sW)[k * 32 + tx];
            #pragma unroll
            for (int i = 0; i < 8; i++) {
                float a = sA[(ty + 8 * i) * 64 + k];
                acc[i][0] += a * w.x;
                acc[i][1] += a * w.y;
                acc[i][2] += a * w.z;
                acc[i][3] += a * w.w;
            }
        }
        __syncthreads();
    }

    int c0 = tx * 4;
    float b0 = bias[c0], b1 = bias[c0 + 1], b2 = bias[c0 + 2], b3 = bias[c0 + 3];
    if (mode == 0) {
        #pragma unroll
        for (int i = 0; i < 8; i++) {
            int r = r0 + ty + 8 * i;
            float4 v;
            v.x = leaky_f(acc[i][0] + b0);
            v.y = leaky_f(acc[i][1] + b1);
            v.z = leaky_f(acc[i][2] + b2);
            v.w = leaky_f(acc[i][3] + b3);
            *(float4*)(AGG + (size_t)r * 128 + c0) = v;
            if (r < NI) *(float4*)(out + (size_t)r * 512 + c0) = v;
        }
    } else {
        float r0c = root[c0], r1c = root[c0 + 1], r2c = root[c0 + 2], r3c = root[c0 + 3];
        #pragma unroll
        for (int i = 0; i < 8; i++) {
            int r = r0 + ty + 8 * i;
            float di = dinv[r];
            float v0 = acc[i][0] + b0, v1 = acc[i][1] + b1;
            float v2 = acc[i][2] + b2, v3 = acc[i][3] + b3;
            float4 p;
            p.x = relu_f(v0); p.y = relu_f(v1); p.z = relu_f(v2); p.w = relu_f(v3);
            *(float4*)(P + (size_t)r * 128 + c0) = p;
            float4 s;
            s.x = relu_f(v0 + r0c) * di;
            s.y = relu_f(v1 + r1c) * di;
            s.z = relu_f(v2 + r2c) * di;
            s.w = relu_f(v3 + r3c) * di;
            *(float4*)(AGG + (size_t)r * 128 + c0) = s;
        }
    }
}

// ---------------- scatter: AGG[col] += dis[row]*dis[col] * P[row], warp per edge ----------------
__global__ void k_scatter(const int* __restrict__ edges, const float* __restrict__ dis,
                          const float* __restrict__ P, float* __restrict__ AGG, int E) {
    int w = (blockIdx.x * blockDim.x + threadIdx.x) >> 5;
    if (w >= E) return;
    int lane = threadIdx.x & 31;
    int row = __ldg(&edges[w]);
    int col = __ldg(&edges[E + w]);
    float nrm = dis[row] * dis[col];
    const float* src = P + (size_t)row * 128;
    float* dst = AGG + (size_t)col * 128;
    #pragma unroll
    for (int i = 0; i < 4; i++) {
        int c = lane + 32 * i;
        atomicAdd(&dst[c], nrm * src[c]);
    }
}

// ---------------- layernorm + leaky + residual, warp per node ----------------
__global__ void k_ln(const float* __restrict__ Bin, const float* __restrict__ gamma,
                     const float* __restrict__ beta, float* __restrict__ h,
                     float* __restrict__ out, int l, int NI) {
    int t = threadIdx.x;
    int lane = t & 31;
    int node = blockIdx.x * 8 + (t >> 5);
    float4 v = ((const float4*)(Bin + (size_t)node * 128))[lane];
    float s = v.x + v.y + v.z + v.w;
    #pragma unroll
    for (int o = 16; o > 0; o >>= 1) s += __shfl_xor_sync(0xffffffffu, s, o);
    float mu = s * (1.0f / 128.0f);
    float dx = v.x - mu, dy = v.y - mu, dz = v.z - mu, dw = v.w - mu;
    float q = dx * dx + dy * dy + dz * dz + dw * dw;
    #pragma unroll
    for (int o = 16; o > 0; o >>= 1) q += __shfl_xor_sync(0xffffffffu, q, o);
    float rs = rsqrtf(q * (1.0f / 128.0f) + 1e-5f);
    float4 gg = ((const float4*)gamma)[lane];
    float4 bb = ((const float4*)beta)[lane];
    float4 hp = ((const float4*)(h + (size_t)node * 128))[lane];
    float4 o4;
    o4.x = leaky_f(dx * rs * gg.x + bb.x) + hp.x;
    o4.y = leaky_f(dy * rs * gg.y + bb.y) + hp.y;
    o4.z = leaky_f(dz * rs * gg.z + bb.z) + hp.z;
    o4.w = leaky_f(dw * rs * gg.w + bb.w) + hp.w;
    ((float4*)(h + (size_t)node * 128))[lane] = o4;
    if (node < NI) ((float4*)(out + (size_t)node * 512 + (l + 1) * 128))[lane] = o4;
}

// ---------------- host ----------------
extern "C" void kernel_launch(void* const* d_in, const int* in_sizes, int n_in,
                              void* d_out, int out_size) {
    const float* x    = (const float*)d_in[0];
    const float* ew1  = (const float*)d_in[1];
    const float* eb1  = (const float*)d_in[2];
    const float* ew2  = (const float*)d_in[3];
    const float* eb2  = (const float*)d_in[4];
    const float* cw   = (const float*)d_in[5];
    const float* cb   = (const float*)d_in[6];
    const float* cr   = (const float*)d_in[7];
    const float* rw   = (const float*)d_in[8];
    const float* rb   = (const float*)d_in[9];
    const float* rr   = (const float*)d_in[10];
    const float* lg   = (const float*)d_in[11];
    const float* lb   = (const float*)d_in[12];
    const int* e_nn   = (const int*)d_in[13];
    const int* e_net  = (const int*)d_in[14];
    float* out = (float*)d_out;

    int E  = in_sizes[13] / 2;
    int NI = out_size / 512;

    float *p_h, *p_P, *p_A, *p_B, *p_H1;
    float *p_deg0, *p_deg1, *p_dis0, *p_dis1, *p_dinv0, *p_dinv1;
    cudaGetSymbolAddress((void**)&p_h, g_h);
    cudaGetSymbolAddress((void**)&p_P, g_P);
    cudaGetSymbolAddress((void**)&p_A, g_A);
    cudaGetSymbolAddress((void**)&p_B, g_B);
    cudaGetSymbolAddress((void**)&p_H1, g_H1);
    cudaGetSymbolAddress((void**)&p_deg0, g_deg0);
    cudaGetSymbolAddress((void**)&p_deg1, g_deg1);
    cudaGetSymbolAddress((void**)&p_dis0, g_dis0);
    cudaGetSymbolAddress((void**)&p_dis1, g_dis1);
    cudaGetSymbolAddress((void**)&p_dinv0, g_dinv0);
    cudaGetSymbolAddress((void**)&p_dinv1, g_dinv1);

    const int nblkN = (NN + 255) / 256;
    const int nblkE = (E + 255) / 256;

    // degree (shared across layers)
    k_initdeg<<<nblkN, 256>>>();
    k_count<<<nblkE, 256>>>(e_nn, p_deg0, E);
    k_count<<<nblkE, 256>>>(e_net, p_deg1, E);
    k_finishdeg<<<nblkN, 256>>>();

    // encoder
    k_enc1<<<NN / 8, 256>>>(x, ew1, eb1);
    k_gemm<<<NN / 64, 256>>>(p_H1, ew2, eb2, nullptr, nullptr, nullptr, p_h, out,
                             256, 0, NI);

    const int scblk = (E * 32 + 255) / 256;
    for (int l = 0; l < 3; l++) {
        k_gemm<<<NN / 64, 256>>>(p_h, cw + l * 16384, cb + l * 128, cr + l * 128,
                                 p_dinv0, p_P, p_A, nullptr, 128, 1, NI);
        k_scatter<<<scblk, 256>>>(e_nn, p_dis0, p_P, p_A, E);
        k_gemm<<<NN / 64, 256>>>(p_A, rw + l * 16384, rb + l * 128, rr + l * 128,
                                 p_dinv1, p_P, p_B, nullptr, 128, 1, NI);
        k_scatter<<<scblk, 256>>>(e_net, p_dis1, p_P, p_B, E);
        k_ln<<<NN / 8, 256>>>(p_B, lg + l * 128, lb + l * 128, p_h, out, l, NI);
    }
}